// round 1
// baseline (speedup 1.0000x reference)
#include <cuda_runtime.h>
#include <cuda_bf16.h>

#ifndef N_ROWS
#define N_ROWS 4194304
#endif

__global__ void __launch_bounds__(256)
linreg_kernel(const float4* __restrict__ x4,
              const float*  __restrict__ w,
              float*        __restrict__ y,
              int n)
{
    int i = blockIdx.x * blockDim.x + threadIdx.x;
    if (i >= n) return;

    // w[0..31] as 8 float4 + bias w[32]; uniform across warp -> broadcast loads
    const float4* w4 = reinterpret_cast<const float4*>(w);
    float4 w0 = __ldg(w4 + 0);
    float4 w1 = __ldg(w4 + 1);
    float4 w2 = __ldg(w4 + 2);
    float4 w3 = __ldg(w4 + 3);
    float4 w4v = __ldg(w4 + 4);
    float4 w5 = __ldg(w4 + 5);
    float4 w6 = __ldg(w4 + 6);
    float4 w7 = __ldg(w4 + 7);
    float bias = __ldg(w + 32);

    const float4* xr = x4 + (size_t)i * 8;
    // 8 independent 16B loads -> MLP=8 per thread
    float4 v0 = __ldg(xr + 0);
    float4 v1 = __ldg(xr + 1);
    float4 v2 = __ldg(xr + 2);
    float4 v3 = __ldg(xr + 3);
    float4 v4 = __ldg(xr + 4);
    float4 v5 = __ldg(xr + 5);
    float4 v6 = __ldg(xr + 6);
    float4 v7 = __ldg(xr + 7);

    // 4 independent accumulator chains to hide FFMA latency
    float a0 = bias, a1 = 0.f, a2 = 0.f, a3 = 0.f;
    a0 = fmaf(v0.x, w0.x, a0); a1 = fmaf(v0.y, w0.y, a1);
    a2 = fmaf(v0.z, w0.z, a2); a3 = fmaf(v0.w, w0.w, a3);
    a0 = fmaf(v1.x, w1.x, a0); a1 = fmaf(v1.y, w1.y, a1);
    a2 = fmaf(v1.z, w1.z, a2); a3 = fmaf(v1.w, w1.w, a3);
    a0 = fmaf(v2.x, w2.x, a0); a1 = fmaf(v2.y, w2.y, a1);
    a2 = fmaf(v2.z, w2.z, a2); a3 = fmaf(v2.w, w2.w, a3);
    a0 = fmaf(v3.x, w3.x, a0); a1 = fmaf(v3.y, w3.y, a1);
    a2 = fmaf(v3.z, w3.z, a2); a3 = fmaf(v3.w, w3.w, a3);
    a0 = fmaf(v4.x, w4v.x, a0); a1 = fmaf(v4.y, w4v.y, a1);
    a2 = fmaf(v4.z, w4v.z, a2); a3 = fmaf(v4.w, w4v.w, a3);
    a0 = fmaf(v5.x, w5.x, a0); a1 = fmaf(v5.y, w5.y, a1);
    a2 = fmaf(v5.z, w5.z, a2); a3 = fmaf(v5.w, w5.w, a3);
    a0 = fmaf(v6.x, w6.x, a0); a1 = fmaf(v6.y, w6.y, a1);
    a2 = fmaf(v6.z, w6.z, a2); a3 = fmaf(v6.w, w6.w, a3);
    a0 = fmaf(v7.x, w7.x, a0); a1 = fmaf(v7.y, w7.y, a1);
    a2 = fmaf(v7.z, w7.z, a2); a3 = fmaf(v7.w, w7.w, a3);

    y[i] = (a0 + a1) + (a2 + a3);
}

extern "C" void kernel_launch(void* const* d_in, const int* in_sizes, int n_in,
                              void* d_out, int out_size)
{
    const float* x = (const float*)d_in[0];   // [N, 32] fp32
    const float* w = (const float*)d_in[1];   // [33, 1] fp32
    float* y = (float*)d_out;                 // [N, 1] fp32

    int n = in_sizes[0] / 32;                 // rows
    int threads = 256;
    int blocks = (n + threads - 1) / threads;
    linreg_kernel<<<blocks, threads>>>(
        reinterpret_cast<const float4*>(x), w, y, n);
}

// round 2
// speedup vs baseline: 1.3985x; 1.3985x over previous
#include <cuda_runtime.h>
#include <cuda_bf16.h>

// y[i] = dot(x[i, 0:32], w[0:32]) + w[32]
// 8 lanes per row: lane = grp*8 + lig; iteration j covers rows row0 + j*4 + grp.
// For fixed j, address = row0*8 + j*32 + lane -> 32 consecutive float4s per warp
// instruction = 512B contiguous = 4 L1 wavefronts (minimum).
__global__ void __launch_bounds__(256)
linreg_kernel(const float4* __restrict__ x4,
              const float*  __restrict__ w,
              float*        __restrict__ y,
              int n)
{
    const int lane = threadIdx.x & 31;
    const int lig  = lane & 7;    // lane-in-group: which float4 of the row
    const int grp  = lane >> 3;   // which of 4 rows this lane helps with

    const int warp = blockIdx.x * (blockDim.x >> 5) + (threadIdx.x >> 5);
    const int row0 = warp << 5;   // 32 rows per warp
    if (row0 >= n) return;

    // weights: lane lig holds w[4*lig .. 4*lig+3]; broadcast-uniform per lig
    const float4 wv  = __ldg(reinterpret_cast<const float4*>(w) + lig);
    const float bias = __ldg(w + 32);

    const float4* base = x4 + (size_t)row0 * 8;

    #pragma unroll
    for (int j = 0; j < 8; ++j) {
        const float4 v = __ldcs(base + j * 32 + lane);   // coalesced, streaming
        float s = fmaf(v.x, wv.x, fmaf(v.y, wv.y, fmaf(v.z, wv.z, v.w * wv.w)));
        // reduce across the 8-lane group (masks 4,2,1 stay inside the group)
        s += __shfl_xor_sync(0xffffffffu, s, 4);
        s += __shfl_xor_sync(0xffffffffu, s, 2);
        s += __shfl_xor_sync(0xffffffffu, s, 1);
        if (lig == 0) {
            const int r = row0 + j * 4 + grp;
            if (r < n) __stcs(y + r, s + bias);
        }
    }
}

extern "C" void kernel_launch(void* const* d_in, const int* in_sizes, int n_in,
                              void* d_out, int out_size)
{
    const float* x = (const float*)d_in[0];   // [N, 32] fp32
    const float* w = (const float*)d_in[1];   // [33, 1] fp32
    float* y = (float*)d_out;                 // [N] fp32

    const int n = in_sizes[0] / 32;           // rows
    const int threads = 256;                  // 8 warps -> 256 rows per block
    const int rows_per_block = (threads / 32) * 32;
    const int blocks = (n + rows_per_block - 1) / rows_per_block;
    linreg_kernel<<<blocks, threads>>>(
        reinterpret_cast<const float4*>(x), w, y, n);
}

// round 3
// speedup vs baseline: 1.6239x; 1.1611x over previous
#include <cuda_runtime.h>
#include <cuda_bf16.h>

// y[i] = dot(x[i, 0:32], w[0:32]) + w[32]
// Layout: 8 lanes per row (lig = lane&7 picks the float4 within the row,
// grp = lane>>3 picks which of 4 rows per iteration). A warp handles 32 rows.
// Phase 1: front-batch all 8 coalesced LDG.128 (MLP=8 per warp).
// Phase 2: per-iteration FMA + 3x shfl_xor butterfly (sum replicated in group).
// Phase 3: register transpose via one shfl -> single coalesced 128B STG per warp.
__global__ void __launch_bounds__(256)
linreg_kernel(const float4* __restrict__ x4,
              const float*  __restrict__ w,
              float*        __restrict__ y,
              int n)
{
    const int lane = threadIdx.x & 31;
    const int lig  = lane & 7;

    const int warp = blockIdx.x * (blockDim.x >> 5) + (threadIdx.x >> 5);
    const int row0 = warp << 5;                 // 32 rows per warp
    if (row0 >= n) return;

    const float4 wv  = __ldg(reinterpret_cast<const float4*>(w) + lig);
    const float bias = __ldg(w + 32);

    const float4* base = x4 + (size_t)row0 * 8 + lane;

    // ---- Phase 1: all loads in flight before any consumer ----
    float4 v0 = __ldcs(base + 0 * 32);
    float4 v1 = __ldcs(base + 1 * 32);
    float4 v2 = __ldcs(base + 2 * 32);
    float4 v3 = __ldcs(base + 3 * 32);
    float4 v4 = __ldcs(base + 4 * 32);
    float4 v5 = __ldcs(base + 5 * 32);
    float4 v6 = __ldcs(base + 6 * 32);
    float4 v7 = __ldcs(base + 7 * 32);

    // ---- Phase 2: partial dot + butterfly within 8-lane group ----
#define DOT_RED(S, V)                                                          \
    float S = fmaf((V).x, wv.x, fmaf((V).y, wv.y, fmaf((V).z, wv.z, (V).w * wv.w))); \
    S += __shfl_xor_sync(0xffffffffu, S, 4);                                   \
    S += __shfl_xor_sync(0xffffffffu, S, 2);                                   \
    S += __shfl_xor_sync(0xffffffffu, S, 1);

    DOT_RED(s0, v0) DOT_RED(s1, v1) DOT_RED(s2, v2) DOT_RED(s3, v3)
    DOT_RED(s4, v4) DOT_RED(s5, v5) DOT_RED(s6, v6) DOT_RED(s7, v7)
#undef DOT_RED

    // ---- Phase 3: lane t wants row t = iteration (t>>2), group (t&3).
    // Source lane u = (t&3)*8 + (t>>2); u's lig == t>>2, so u exports s[lig].
    float val = s0;
    val = (lig == 1) ? s1 : val;
    val = (lig == 2) ? s2 : val;
    val = (lig == 3) ? s3 : val;
    val = (lig == 4) ? s4 : val;
    val = (lig == 5) ? s5 : val;
    val = (lig == 6) ? s6 : val;
    val = (lig == 7) ? s7 : val;

    const int src = ((lane & 3) << 3) | (lane >> 2);
    float out = __shfl_sync(0xffffffffu, val, src) + bias;

    const int r = row0 + lane;
    if (r < n) __stcs(y + r, out);   // 128B coalesced per warp
}

extern "C" void kernel_launch(void* const* d_in, const int* in_sizes, int n_in,
                              void* d_out, int out_size)
{
    const float* x = (const float*)d_in[0];   // [N, 32] fp32
    const float* w = (const float*)d_in[1];   // [33, 1] fp32
    float* y = (float*)d_out;                 // [N] fp32

    const int n = in_sizes[0] / 32;           // rows
    const int threads = 256;                  // 8 warps -> 256 rows/block
    const int rows_per_block = (threads / 32) * 32;
    const int blocks = (n + rows_per_block - 1) / rows_per_block;
    linreg_kernel<<<blocks, threads>>>(
        reinterpret_cast<const float4*>(x), w, y, n);
}